// round 6
// baseline (speedup 1.0000x reference)
#include <cuda_runtime.h>
#include <cuda_bf16.h>
#include <math.h>
#include <stdint.h>

// Problem constants
#define B_    16
#define T_    1000
#define INDIM 257
#define FEAT  771
#define H_    512
#define H3    1536
#define KN    9
#define KS    6
#define M_    (B_*T_)        // 16000
#define FOUT  (H_*KN)        // 4608
#define PF    5              // scan prefetch depth (float4 slots; 1000 % 5 == 0)
#define TT    4              // conv timesteps per block

// ---------------- scratch (device globals; no runtime allocation) ------------
__device__ float g_X0[T_*B_*H_];
__device__ float g_U [T_*B_*H3];
__device__ float g_X1[T_*B_*H_];
__device__ float g_X2[T_*B_*H_];
__device__ float g_hmax[B_*KN*T_*H_];
__device__ float g_Y [M_*FOUT];
// bf16 hi/lo weight copies, K-major (N rows x Kp cols), zero-padded
__device__ __nv_bfloat16 g_BinH [512*800],     g_BinL [512*800];
__device__ __nv_bfloat16 g_BrnnH[2*1536*512],  g_BrnnL[2*1536*512];
__device__ __nv_bfloat16 g_BoutH[384*4608],    g_BoutL[384*4608];

__device__ __forceinline__ float sigf(float x) { return 1.f / (1.f + __expf(-x)); }

__device__ __forceinline__ uint32_t pk(__nv_bfloat16 a, __nv_bfloat16 b) {
    return (uint32_t)__bfloat16_as_ushort(b) << 16 | __bfloat16_as_ushort(a);
}
__device__ __forceinline__ void mma16816(float* d, const uint32_t* a,
                                         const uint32_t* b) {
    asm volatile(
        "mma.sync.aligned.m16n8k16.row.col.f32.bf16.bf16.f32 "
        "{%0,%1,%2,%3}, {%4,%5,%6,%7}, {%8,%9}, {%0,%1,%2,%3};"
        : "+f"(d[0]), "+f"(d[1]), "+f"(d[2]), "+f"(d[3])
        : "r"(a[0]), "r"(a[1]), "r"(a[2]), "r"(a[3]), "r"(b[0]), "r"(b[1]));
}

// ---------------- tensor-core GEMM (mma.sync bf16, 2-term fp32 split) --------
// (unchanged from round 5 — proven)
template <int MODE>
__global__ __launch_bounds__(256) void hgemm(
    const float* __restrict__ A,
    const __nv_bfloat16* __restrict__ Bh, const __nv_bfloat16* __restrict__ Bl,
    float* __restrict__ C, int Kreal, int Kp, int lda, int ldc, int Ncols,
    const float* __restrict__ bias, const float* __restrict__ gate)
{
    __shared__ uint32_t Ah_s[128*16], Al_s[128*16];
    __shared__ uint32_t Bh_s[128*16], Bl_s[128*16];

    const int tid  = threadIdx.x;
    const int m0   = blockIdx.y * 128;
    const int n0   = blockIdx.x * 128;
    const int wid  = tid >> 5, lane = tid & 31;
    const int wm   = wid >> 2, wn = wid & 3;
    const int quad = lane >> 2, qc = lane & 3;
    const int swq  = quad << 1;

    const int row = tid >> 1, hf = tid & 1;
    const float* Arow = A + (size_t)(m0 + row) * lda + hf * 16;
    const __nv_bfloat16* BhR = Bh + (size_t)(n0 + row) * Kp + hf * 16;
    const __nv_bfloat16* BlR = Bl + (size_t)(n0 + row) * Kp + hf * 16;
    const bool vec = ((lda & 3) == 0) && (Kreal == Kp);

    float acc[4][4][4];
    #pragma unroll
    for (int i = 0; i < 4; ++i)
        #pragma unroll
        for (int j = 0; j < 4; ++j)
            #pragma unroll
            for (int q = 0; q < 4; ++q) acc[i][j][q] = 0.f;

    float ar[16];
    uint4 bhv[2], blv[2];

    {
        if (vec) {
            const float4* p = (const float4*)Arow;
            float4 v0 = p[0], v1 = p[1], v2 = p[2], v3 = p[3];
            ar[0]=v0.x; ar[1]=v0.y; ar[2]=v0.z; ar[3]=v0.w;
            ar[4]=v1.x; ar[5]=v1.y; ar[6]=v1.z; ar[7]=v1.w;
            ar[8]=v2.x; ar[9]=v2.y; ar[10]=v2.z; ar[11]=v2.w;
            ar[12]=v3.x; ar[13]=v3.y; ar[14]=v3.z; ar[15]=v3.w;
        } else {
            #pragma unroll
            for (int t = 0; t < 16; ++t)
                ar[t] = (hf * 16 + t < Kreal) ? Arow[t] : 0.f;
        }
        bhv[0] = ((const uint4*)BhR)[0]; bhv[1] = ((const uint4*)BhR)[1];
        blv[0] = ((const uint4*)BlR)[0]; blv[1] = ((const uint4*)BlR)[1];
    }

    const int nchunks = Kp / 32;
    const int sw_r = (row & 7) << 1;

    for (int ic = 0; ic < nchunks; ++ic) {
        __syncthreads();
        #pragma unroll
        for (int j = 0; j < 8; ++j) {
            float a0 = ar[2*j], a1 = ar[2*j+1];
            __nv_bfloat16 h0 = __float2bfloat16(a0);
            __nv_bfloat16 h1 = __float2bfloat16(a1);
            __nv_bfloat16 l0 = __float2bfloat16(a0 - __bfloat162float(h0));
            __nv_bfloat16 l1 = __float2bfloat16(a1 - __bfloat162float(h1));
            const int idx = row * 16 + ((hf * 8 + j) ^ sw_r);
            Ah_s[idx] = pk(h0, h1);
            Al_s[idx] = pk(l0, l1);
        }
        {
            const uint32_t* bw = (const uint32_t*)bhv;
            const uint32_t* cw = (const uint32_t*)blv;
            #pragma unroll
            for (int j = 0; j < 8; ++j) {
                const int idx = row * 16 + ((hf * 8 + j) ^ sw_r);
                Bh_s[idx] = bw[j];
                Bl_s[idx] = cw[j];
            }
        }
        __syncthreads();

        if (ic + 1 < nchunks) {
            const int k0 = (ic + 1) * 32;
            if (vec) {
                const float4* p = (const float4*)(Arow + k0);
                float4 v0 = p[0], v1 = p[1], v2 = p[2], v3 = p[3];
                ar[0]=v0.x; ar[1]=v0.y; ar[2]=v0.z; ar[3]=v0.w;
                ar[4]=v1.x; ar[5]=v1.y; ar[6]=v1.z; ar[7]=v1.w;
                ar[8]=v2.x; ar[9]=v2.y; ar[10]=v2.z; ar[11]=v2.w;
                ar[12]=v3.x; ar[13]=v3.y; ar[14]=v3.z; ar[15]=v3.w;
            } else {
                #pragma unroll
                for (int t = 0; t < 16; ++t)
                    ar[t] = (k0 + hf * 16 + t < Kreal) ? Arow[k0 + t] : 0.f;
            }
            bhv[0] = ((const uint4*)(BhR + k0))[0];
            bhv[1] = ((const uint4*)(BhR + k0))[1];
            blv[0] = ((const uint4*)(BlR + k0))[0];
            blv[1] = ((const uint4*)(BlR + k0))[1];
        }

        #pragma unroll
        for (int kt = 0; kt < 2; ++kt) {
            const int w0 = kt * 8 + qc, w1 = kt * 8 + 4 + qc;
            uint32_t af[4][4], alf[4][4];
            #pragma unroll
            for (int i = 0; i < 4; ++i) {
                const int r0 = wm * 64 + i * 16 + quad, r1 = r0 + 8;
                const int i00 = r0*16 + (w0^swq), i10 = r1*16 + (w0^swq);
                const int i01 = r0*16 + (w1^swq), i11 = r1*16 + (w1^swq);
                af[i][0]=Ah_s[i00]; af[i][1]=Ah_s[i10];
                af[i][2]=Ah_s[i01]; af[i][3]=Ah_s[i11];
                alf[i][0]=Al_s[i00]; alf[i][1]=Al_s[i10];
                alf[i][2]=Al_s[i01]; alf[i][3]=Al_s[i11];
            }
            uint32_t bfh[4][2], bfl[4][2];
            #pragma unroll
            for (int j = 0; j < 4; ++j) {
                const int rn = wn * 32 + j * 8 + quad;
                const int i0 = rn*16 + (w0^swq), i1 = rn*16 + (w1^swq);
                bfh[j][0]=Bh_s[i0]; bfh[j][1]=Bh_s[i1];
                bfl[j][0]=Bl_s[i0]; bfl[j][1]=Bl_s[i1];
            }
            #pragma unroll
            for (int i = 0; i < 4; ++i)
                #pragma unroll
                for (int j = 0; j < 4; ++j) {
                    mma16816(acc[i][j], af[i],  bfh[j]);
                    mma16816(acc[i][j], af[i],  bfl[j]);
                    mma16816(acc[i][j], alf[i], bfh[j]);
                }
        }
    }

    #pragma unroll
    for (int i = 0; i < 4; ++i) {
        #pragma unroll
        for (int j = 0; j < 4; ++j) {
            const int r0 = m0 + wm * 64 + i * 16 + quad, r1 = r0 + 8;
            const int cc = n0 + wn * 32 + j * 8 + 2 * qc;
            const float* d = acc[i][j];
            if (MODE == 0) {
                *(float2*)(C + (size_t)r0 * ldc + cc) = make_float2(d[0], d[1]);
                *(float2*)(C + (size_t)r1 * ldc + cc) = make_float2(d[2], d[3]);
            } else if (MODE == 1) {
                const int o0 = (r0 % T_) * B_ + (r0 / T_);
                const int o1 = (r1 % T_) * B_ + (r1 / T_);
                const float b0 = bias[cc], b1 = bias[cc + 1];
                *(float2*)(C + (size_t)o0 * H_ + cc) =
                    make_float2(tanhf(d[0] + b0), tanhf(d[1] + b1));
                *(float2*)(C + (size_t)o1 * H_ + cc) =
                    make_float2(tanhf(d[2] + b0), tanhf(d[3] + b1));
            } else {
                #pragma unroll
                for (int q = 0; q < 2; ++q) {
                    const int c = cc + q;
                    if (c < Ncols) {
                        float s0 = sigf(d[q] + bias[c]);
                        float s1 = sigf(d[2 + q] + bias[c]);
                        C[(size_t)r0 * INDIM + c] =
                            s0 * gate[(size_t)r0 * FEAT + INDIM + c];
                        C[(size_t)r1 * INDIM + c] =
                            s1 * gate[(size_t)r1 * FEAT + INDIM + c];
                    }
                }
            }
        }
    }
}

// ---------------- weight prep: transpose to K-major + bf16 hi/lo split -------
__global__ void prep_w(const float* __restrict__ W, __nv_bfloat16* __restrict__ Bh,
                       __nv_bfloat16* __restrict__ Bl, int K, int N, int Kp)
{
    int i = blockIdx.x * blockDim.x + threadIdx.x;
    if (i >= N * Kp) return;
    int n = i / Kp, k = i % Kp;
    float v = (k < K) ? W[(size_t)k * N + n] : 0.f;
    __nv_bfloat16 h = __float2bfloat16(v);
    Bh[i] = h;
    Bl[i] = __float2bfloat16(v - __bfloat162float(h));
}
// Feature axis permuted: k' = o*H + h corresponds to original k = h*KN + o.
// (Matches pool_t's coalesced Y layout.)
__global__ void prep_wout(const float* __restrict__ Wout,
                          __nv_bfloat16* __restrict__ Bh,
                          __nv_bfloat16* __restrict__ Bl)
{
    int i = blockIdx.x * blockDim.x + threadIdx.x;
    if (i >= 384 * 4608) return;
    int n = i / 4608, kp = i % 4608;
    int o = kp / H_, h = kp % H_;
    int k = h * KN + o;
    float v = (n < INDIM) ? Wout[(size_t)k * FEAT + INDIM + n] : 0.f;
    __nv_bfloat16 hh = __float2bfloat16(v);
    Bh[i] = hh;
    Bl[i] = __float2bfloat16(v - __bfloat162float(hh));
}

// ---------------- SRU recurrence: 1 thread per (b, 4 adjacent h), float4 -----
#define SRU1(comp) { \
    float f  = sigf(fp.comp + vf.comp * c4.comp + bf4.comp);               \
    float rr = sigf(rp.comp + vr.comp * c4.comp + br4.comp);               \
    float cn = f * c4.comp + (1.f - f) * xt.comp;                          \
    o4.comp = rr * cn + (1.f - rr) * xin.comp;                             \
    c4.comp = cn; }

__global__ __launch_bounds__(64) void sru_scan4(
    const float* __restrict__ U, const float* __restrict__ X,
    float* __restrict__ Xout,
    const float* __restrict__ v, const float* __restrict__ bb)
{
    int g  = blockIdx.x * 64 + threadIdx.x;     // 0 .. B*H/4-1 (2048)
    int b  = g >> 7;                            // / (H/4)
    int hq = g & 127;
    int h  = hq * 4;

    const float4 vf  = *(const float4*)(v  + h);
    const float4 vr  = *(const float4*)(v  + H_ + h);
    const float4 bf4 = *(const float4*)(bb + h);
    const float4 br4 = *(const float4*)(bb + H_ + h);

    const float4* Uxt = (const float4*)(U + (size_t)b * H3 + h);          // xt
    const float4* Ufp = Uxt + H_ / 4;                                     // fp
    const float4* Urp = Uxt + 2 * (H_ / 4);                               // rp
    const float4* Xb  = (const float4*)(X + (size_t)b * H_ + h);
    float4*       Ob  = (float4*)(Xout + (size_t)b * H_ + h);
    const int SU = B_ * H3 / 4;      // per-t stride in float4
    const int SX = B_ * H_ / 4;

    float4 pxt[PF], pfp[PF], prp[PF], pxin[PF];
    #pragma unroll
    for (int i = 0; i < PF; ++i) {
        pxt[i]  = Uxt[(size_t)i * SU];
        pfp[i]  = Ufp[(size_t)i * SU];
        prp[i]  = Urp[(size_t)i * SU];
        pxin[i] = Xb [(size_t)i * SX];
    }

    float4 c4 = make_float4(0.f, 0.f, 0.f, 0.f);
    for (int t0 = 0; t0 < T_; t0 += PF) {
        #pragma unroll
        for (int i = 0; i < PF; ++i) {
            int t = t0 + i;
            float4 xt = pxt[i], fp = pfp[i], rp = prp[i], xin = pxin[i];
            int tp = t + PF;
            if (tp < T_) {
                pxt[i]  = Uxt[(size_t)tp * SU];
                pfp[i]  = Ufp[(size_t)tp * SU];
                prp[i]  = Urp[(size_t)tp * SU];
                pxin[i] = Xb [(size_t)tp * SX];
            }
            float4 o4;
            SRU1(x) SRU1(y) SRU1(z) SRU1(w)
            Ob[(size_t)t * SX] = o4;
        }
    }
}

// -------- fused conv 6x6 (9ch, pad 3/2) + bias + tanh + h-pool, TT t/block ---
__global__ __launch_bounds__(512) void conv_pool_h(
    const float* __restrict__ X, const float* __restrict__ Wk,
    const float* __restrict__ cb, float* __restrict__ out)
{
    __shared__ float sw[KN * KS * KS];
    __shared__ float xs[KS + TT - 1][H_ + 6];    // rows t0-3 .. t0+TT+1
    __shared__ float buf[KN][H_ + 2];

    const int h  = threadIdx.x;
    const int t0 = blockIdx.x * TT;
    const int b  = blockIdx.y;

    for (int i = h; i < KN * KS * KS; i += 512) sw[i] = Wk[i];

    #pragma unroll
    for (int p = 0; p < KS + TT - 1; ++p) {
        int tt = t0 - 3 + p;
        const float* rowp = X + (size_t)(tt * B_ + b) * H_;
        bool tok = (tt >= 0 && tt < T_);
        for (int idx = h; idx < H_ + 6; idx += 512) {
            int hh = idx - 3;
            xs[p][idx] = (tok && hh >= 0 && hh < H_) ? rowp[hh] : 0.f;
        }
    }
    if (h < KN) { buf[h][0] = -INFINITY; buf[h][H_ + 1] = -INFINITY; }
    __syncthreads();

    #pragma unroll
    for (int dt = 0; dt < TT; ++dt) {
        float acc[KN];
        #pragma unroll
        for (int o = 0; o < KN; ++o) acc[o] = 0.f;
        #pragma unroll
        for (int p = 0; p < KS; ++p) {
            float xv[KS];
            #pragma unroll
            for (int q = 0; q < KS; ++q) xv[q] = xs[dt + p][h + q];
            #pragma unroll
            for (int q = 0; q < KS; ++q) {
                float x = xv[q];
                #pragma unroll
                for (int o = 0; o < KN; ++o)
                    acc[o] = fmaf(x, sw[o * 36 + p * 6 + q], acc[o]);
            }
        }
        #pragma unroll
        for (int o = 0; o < KN; ++o) buf[o][h + 1] = tanhf(acc[o] + cb[o]);
        __syncthreads();
        const int t = t0 + dt;
        #pragma unroll
        for (int o = 0; o < KN; ++o) {
            float m = fmaxf(fmaxf(buf[o][h], buf[o][h + 1]), buf[o][h + 2]);
            out[((size_t)(b * KN + o) * T_ + t) * H_ + h] = m;
        }
        __syncthreads();    // buf reuse hazard for next dt
    }
}

// t-direction max + transpose into (B*T, H*KN), feature = o*H + h (coalesced)
__global__ void pool_t(const float* __restrict__ in, float* __restrict__ Y)
{
    int h  = blockIdx.x * blockDim.x + threadIdx.x;
    int t  = blockIdx.y;
    int bk = blockIdx.z;
    int b  = bk / KN, o = bk % KN;
    size_t base = ((size_t)bk * T_ + t) * H_ + h;
    float m = in[base];
    if (t > 0)      m = fmaxf(m, in[base - H_]);
    if (t < T_ - 1) m = fmaxf(m, in[base + H_]);
    Y[((size_t)(b * T_ + t)) * FOUT + o * H_ + h] = m;
}

// ---------------- launch ------------------------------------------------------
extern "C" void kernel_launch(void* const* d_in, const int* in_sizes, int n_in,
                              void* d_out, int out_size)
{
    const float* inputs = (const float*)d_in[0];
    const float* W_in   = (const float*)d_in[1];
    const float* b_in   = (const float*)d_in[2];
    const float* W_rnn  = (const float*)d_in[3];
    const float* v_rnn  = (const float*)d_in[4];
    const float* b_rnn  = (const float*)d_in[5];
    const float* conv_k = (const float*)d_in[6];
    const float* conv_b = (const float*)d_in[7];
    const float* W_out  = (const float*)d_in[8];
    const float* b_out  = (const float*)d_in[9];
    float* out = (float*)d_out;

    float *X0, *U, *X1, *X2, *HM, *Y;
    __nv_bfloat16 *BinH, *BinL, *BrnnH, *BrnnL, *BoutH, *BoutL;
    cudaGetSymbolAddress((void**)&X0,   g_X0);
    cudaGetSymbolAddress((void**)&U,    g_U);
    cudaGetSymbolAddress((void**)&X1,   g_X1);
    cudaGetSymbolAddress((void**)&X2,   g_X2);
    cudaGetSymbolAddress((void**)&HM,   g_hmax);
    cudaGetSymbolAddress((void**)&Y,    g_Y);
    cudaGetSymbolAddress((void**)&BinH, g_BinH);
    cudaGetSymbolAddress((void**)&BinL, g_BinL);
    cudaGetSymbolAddress((void**)&BrnnH,g_BrnnH);
    cudaGetSymbolAddress((void**)&BrnnL,g_BrnnL);
    cudaGetSymbolAddress((void**)&BoutH,g_BoutH);
    cudaGetSymbolAddress((void**)&BoutL,g_BoutL);

    // weight prep (K-major bf16 hi/lo)
    prep_w<<<(512*800 + 255)/256, 256>>>(W_in, BinH, BinL, FEAT, H_, 800);
    prep_w<<<(1536*512 + 255)/256, 256>>>(W_rnn, BrnnH, BrnnL, H_, H3, 512);
    prep_w<<<(1536*512 + 255)/256, 256>>>(W_rnn + H_*H3, BrnnH + 1536*512,
                                          BrnnL + 1536*512, H_, H3, 512);
    prep_wout<<<(384*4608 + 255)/256, 256>>>(W_out, BoutH, BoutL);

    // input layer: tanh(inputs @ W_in + b_in) -> X0 (T,B,H)
    hgemm<1><<<dim3(4, 125), 256>>>(
        inputs, BinH, BinL, X0, FEAT, 800, FEAT, H_, H_, b_in, nullptr);

    // SRU layer 0
    hgemm<0><<<dim3(12, 125), 256>>>(
        X0, BrnnH, BrnnL, U, H_, 512, H_, H3, H3, nullptr, nullptr);
    sru_scan4<<<(B_*H_/4)/64, 64>>>(U, X0, X1, v_rnn, b_rnn);

    // SRU layer 1
    hgemm<0><<<dim3(12, 125), 256>>>(
        X1, BrnnH + 1536*512, BrnnL + 1536*512, U, H_, 512, H_, H3, H3,
        nullptr, nullptr);
    sru_scan4<<<(B_*H_/4)/64, 64>>>(U, X1, X2, v_rnn + 2*H_, b_rnn + 2*H_);

    // fused conv + bias + tanh + h-pool (TT timesteps per block)
    conv_pool_h<<<dim3(T_/TT, B_), 512>>>(X2, conv_k, conv_b, HM);

    // t-pool + transpose to (B*T, o*H + h) — fully coalesced
    pool_t<<<dim3(H_/256, T_, B_*KN), 256>>>(HM, Y);

    // output GEMM (257 live cols, padded to 384) + sigmoid gate * inputs
    hgemm<2><<<dim3(3, 125), 256>>>(
        Y, BoutH, BoutL, out, FOUT, FOUT, FOUT, INDIM, INDIM,
        b_out + INDIM, inputs);
}

// round 8
// speedup vs baseline: 1.2752x; 1.2752x over previous
#include <cuda_runtime.h>
#include <cuda_bf16.h>
#include <math.h>
#include <stdint.h>

// Problem constants
#define B_    16
#define T_    1000
#define INDIM 257
#define FEAT  771
#define H_    512
#define H3    1536
#define KN    9
#define KS    6
#define M_    (B_*T_)        // 16000
#define FOUT  (H_*KN)        // 4608
#define TT    4              // conv timesteps per block
#define D_    24             // scan cp.async ring depth

// ---------------- scratch (device globals; no runtime allocation) ------------
__device__ float g_X0[T_*B_*H_];
__device__ float g_U [T_*B_*H3];
__device__ float g_X1[T_*B_*H_];
__device__ float g_X2[T_*B_*H_];
__device__ float g_hmax[B_*KN*T_*H_];
__device__ float g_Y [M_*FOUT];
// bf16 hi/lo weight copies, K-major (N rows x Kp cols), zero-padded
__device__ __nv_bfloat16 g_BinH [512*800],     g_BinL [512*800];
__device__ __nv_bfloat16 g_BrnnH[2*1536*512],  g_BrnnL[2*1536*512];
__device__ __nv_bfloat16 g_BoutH[384*4608],    g_BoutL[384*4608];

__device__ __forceinline__ float sigf(float x) { return 1.f / (1.f + __expf(-x)); }

__device__ __forceinline__ uint32_t pk(__nv_bfloat16 a, __nv_bfloat16 b) {
    return (uint32_t)__bfloat16_as_ushort(b) << 16 | __bfloat16_as_ushort(a);
}
__device__ __forceinline__ void mma16816(float* d, const uint32_t* a,
                                         const uint32_t* b) {
    asm volatile(
        "mma.sync.aligned.m16n8k16.row.col.f32.bf16.bf16.f32 "
        "{%0,%1,%2,%3}, {%4,%5,%6,%7}, {%8,%9}, {%0,%1,%2,%3};"
        : "+f"(d[0]), "+f"(d[1]), "+f"(d[2]), "+f"(d[3])
        : "r"(a[0]), "r"(a[1]), "r"(a[2]), "r"(a[3]), "r"(b[0]), "r"(b[1]));
}

// cp.async helpers
__device__ __forceinline__ void cp4(uint32_t dst, const float* src) {
    asm volatile("cp.async.ca.shared.global [%0], [%1], 4;"
                 :: "r"(dst), "l"(src) : "memory");
}
__device__ __forceinline__ void cp_commit() {
    asm volatile("cp.async.commit_group;" ::: "memory");
}
template <int N>
__device__ __forceinline__ void cp_wait() {
    asm volatile("cp.async.wait_group %0;" :: "n"(N) : "memory");
}

// ---------------- tensor-core GEMM (mma.sync bf16, 2-term fp32 split) --------
template <int MODE>
__global__ __launch_bounds__(256) void hgemm(
    const float* __restrict__ A,
    const __nv_bfloat16* __restrict__ Bh, const __nv_bfloat16* __restrict__ Bl,
    float* __restrict__ C, int Kreal, int Kp, int lda, int ldc, int Ncols,
    const float* __restrict__ bias, const float* __restrict__ gate)
{
    __shared__ uint32_t Ah_s[128*16], Al_s[128*16];
    __shared__ uint32_t Bh_s[128*16], Bl_s[128*16];

    const int tid  = threadIdx.x;
    const int m0   = blockIdx.y * 128;
    const int n0   = blockIdx.x * 128;
    const int wid  = tid >> 5, lane = tid & 31;
    const int wm   = wid >> 2, wn = wid & 3;
    const int quad = lane >> 2, qc = lane & 3;
    const int swq  = quad << 1;

    const int row = tid >> 1, hf = tid & 1;
    const float* Arow = A + (size_t)(m0 + row) * lda + hf * 16;
    const __nv_bfloat16* BhR = Bh + (size_t)(n0 + row) * Kp + hf * 16;
    const __nv_bfloat16* BlR = Bl + (size_t)(n0 + row) * Kp + hf * 16;
    const bool vec = ((lda & 3) == 0) && (Kreal == Kp);

    float acc[4][4][4];
    #pragma unroll
    for (int i = 0; i < 4; ++i)
        #pragma unroll
        for (int j = 0; j < 4; ++j)
            #pragma unroll
            for (int q = 0; q < 4; ++q) acc[i][j][q] = 0.f;

    float ar[16];
    uint4 bhv[2], blv[2];

    {
        if (vec) {
            const float4* p = (const float4*)Arow;
            float4 v0 = p[0], v1 = p[1], v2 = p[2], v3 = p[3];
            ar[0]=v0.x; ar[1]=v0.y; ar[2]=v0.z; ar[3]=v0.w;
            ar[4]=v1.x; ar[5]=v1.y; ar[6]=v1.z; ar[7]=v1.w;
            ar[8]=v2.x; ar[9]=v2.y; ar[10]=v2.z; ar[11]=v2.w;
            ar[12]=v3.x; ar[13]=v3.y; ar[14]=v3.z; ar[15]=v3.w;
        } else {
            #pragma unroll
            for (int t = 0; t < 16; ++t)
                ar[t] = (hf * 16 + t < Kreal) ? Arow[t] : 0.f;
        }
        bhv[0] = ((const uint4*)BhR)[0]; bhv[1] = ((const uint4*)BhR)[1];
        blv[0] = ((const uint4*)BlR)[0]; blv[1] = ((const uint4*)BlR)[1];
    }

    const int nchunks = Kp / 32;
    const int sw_r = (row & 7) << 1;

    for (int ic = 0; ic < nchunks; ++ic) {
        __syncthreads();
        #pragma unroll
        for (int j = 0; j < 8; ++j) {
            float a0 = ar[2*j], a1 = ar[2*j+1];
            __nv_bfloat16 h0 = __float2bfloat16(a0);
            __nv_bfloat16 h1 = __float2bfloat16(a1);
            __nv_bfloat16 l0 = __float2bfloat16(a0 - __bfloat162float(h0));
            __nv_bfloat16 l1 = __float2bfloat16(a1 - __bfloat162float(h1));
            const int idx = row * 16 + ((hf * 8 + j) ^ sw_r);
            Ah_s[idx] = pk(h0, h1);
            Al_s[idx] = pk(l0, l1);
        }
        {
            const uint32_t* bw = (const uint32_t*)bhv;
            const uint32_t* cw = (const uint32_t*)blv;
            #pragma unroll
            for (int j = 0; j < 8; ++j) {
                const int idx = row * 16 + ((hf * 8 + j) ^ sw_r);
                Bh_s[idx] = bw[j];
                Bl_s[idx] = cw[j];
            }
        }
        __syncthreads();

        if (ic + 1 < nchunks) {
            const int k0 = (ic + 1) * 32;
            if (vec) {
                const float4* p = (const float4*)(Arow + k0);
                float4 v0 = p[0], v1 = p[1], v2 = p[2], v3 = p[3];
                ar[0]=v0.x; ar[1]=v0.y; ar[2]=v0.z; ar[3]=v0.w;
                ar[4]=v1.x; ar[5]=v1.y; ar[6]=v1.z; ar[7]=v1.w;
                ar[8]=v2.x; ar[9]=v2.y; ar[10]=v2.z; ar[11]=v2.w;
                ar[12]=v3.x; ar[13]=v3.y; ar[14]=v3.z; ar[15]=v3.w;
            } else {
                #pragma unroll
                for (int t = 0; t < 16; ++t)
                    ar[t] = (k0 + hf * 16 + t < Kreal) ? Arow[k0 + t] : 0.f;
            }
            bhv[0] = ((const uint4*)(BhR + k0))[0];
            bhv[1] = ((const uint4*)(BhR + k0))[1];
            blv[0] = ((const uint4*)(BlR + k0))[0];
            blv[1] = ((const uint4*)(BlR + k0))[1];
        }

        #pragma unroll
        for (int kt = 0; kt < 2; ++kt) {
            const int w0 = kt * 8 + qc, w1 = kt * 8 + 4 + qc;
            uint32_t af[4][4], alf[4][4];
            #pragma unroll
            for (int i = 0; i < 4; ++i) {
                const int r0 = wm * 64 + i * 16 + quad, r1 = r0 + 8;
                const int i00 = r0*16 + (w0^swq), i10 = r1*16 + (w0^swq);
                const int i01 = r0*16 + (w1^swq), i11 = r1*16 + (w1^swq);
                af[i][0]=Ah_s[i00]; af[i][1]=Ah_s[i10];
                af[i][2]=Ah_s[i01]; af[i][3]=Ah_s[i11];
                alf[i][0]=Al_s[i00]; alf[i][1]=Al_s[i10];
                alf[i][2]=Al_s[i01]; alf[i][3]=Al_s[i11];
            }
            uint32_t bfh[4][2], bfl[4][2];
            #pragma unroll
            for (int j = 0; j < 4; ++j) {
                const int rn = wn * 32 + j * 8 + quad;
                const int i0 = rn*16 + (w0^swq), i1 = rn*16 + (w1^swq);
                bfh[j][0]=Bh_s[i0]; bfh[j][1]=Bh_s[i1];
                bfl[j][0]=Bl_s[i0]; bfl[j][1]=Bl_s[i1];
            }
            #pragma unroll
            for (int i = 0; i < 4; ++i)
                #pragma unroll
                for (int j = 0; j < 4; ++j) {
                    mma16816(acc[i][j], af[i],  bfh[j]);
                    mma16816(acc[i][j], af[i],  bfl[j]);
                    mma16816(acc[i][j], alf[i], bfh[j]);
                }
        }
    }

    #pragma unroll
    for (int i = 0; i < 4; ++i) {
        #pragma unroll
        for (int j = 0; j < 4; ++j) {
            const int r0 = m0 + wm * 64 + i * 16 + quad, r1 = r0 + 8;
            const int cc = n0 + wn * 32 + j * 8 + 2 * qc;
            const float* d = acc[i][j];
            if (MODE == 0) {
                *(float2*)(C + (size_t)r0 * ldc + cc) = make_float2(d[0], d[1]);
                *(float2*)(C + (size_t)r1 * ldc + cc) = make_float2(d[2], d[3]);
            } else if (MODE == 1) {
                const int o0 = (r0 % T_) * B_ + (r0 / T_);
                const int o1 = (r1 % T_) * B_ + (r1 / T_);
                const float b0 = bias[cc], b1 = bias[cc + 1];
                *(float2*)(C + (size_t)o0 * H_ + cc) =
                    make_float2(tanhf(d[0] + b0), tanhf(d[1] + b1));
                *(float2*)(C + (size_t)o1 * H_ + cc) =
                    make_float2(tanhf(d[2] + b0), tanhf(d[3] + b1));
            } else {
                #pragma unroll
                for (int q = 0; q < 2; ++q) {
                    const int c = cc + q;
                    if (c < Ncols) {
                        float s0 = sigf(d[q] + bias[c]);
                        float s1 = sigf(d[2 + q] + bias[c]);
                        C[(size_t)r0 * INDIM + c] =
                            s0 * gate[(size_t)r0 * FEAT + INDIM + c];
                        C[(size_t)r1 * INDIM + c] =
                            s1 * gate[(size_t)r1 * FEAT + INDIM + c];
                    }
                }
            }
        }
    }
}

// ---------------- weight prep -------------------------------------------------
__global__ void prep_w(const float* __restrict__ W, __nv_bfloat16* __restrict__ Bh,
                       __nv_bfloat16* __restrict__ Bl, int K, int N, int Kp)
{
    int i = blockIdx.x * blockDim.x + threadIdx.x;
    if (i >= N * Kp) return;
    int n = i / Kp, k = i % Kp;
    float v = (k < K) ? W[(size_t)k * N + n] : 0.f;
    __nv_bfloat16 h = __float2bfloat16(v);
    Bh[i] = h;
    Bl[i] = __float2bfloat16(v - __bfloat162float(h));
}
// Feature axis permuted: k' = o*H + h corresponds to original k = h*KN + o.
__global__ void prep_wout(const float* __restrict__ Wout,
                          __nv_bfloat16* __restrict__ Bh,
                          __nv_bfloat16* __restrict__ Bl)
{
    int i = blockIdx.x * blockDim.x + threadIdx.x;
    if (i >= 384 * 4608) return;
    int n = i / 4608, kp = i % 4608;
    int o = kp / H_, h = kp % H_;
    int k = h * KN + o;
    float v = (n < INDIM) ? Wout[(size_t)k * FEAT + INDIM + n] : 0.f;
    __nv_bfloat16 hh = __float2bfloat16(v);
    Bh[i] = hh;
    Bl[i] = __float2bfloat16(v - __bfloat162float(hh));
}

// ------- SRU recurrence: 1 thread/chain, cp.async ring (depth D_) ------------
__global__ __launch_bounds__(64) void sru_scan_ca(
    const float* __restrict__ U, const float* __restrict__ X,
    float* __restrict__ Xout,
    const float* __restrict__ v, const float* __restrict__ bb)
{
    __shared__ float ring[D_][64][4];

    const int tid = threadIdx.x;
    const int g = blockIdx.x * 64 + tid;
    const int b = g / H_, h = g % H_;
    const float vf = v[h],  vr = v[H_ + h];
    const float bf = bb[h], br = bb[H_ + h];
    const float* Ub = U + (size_t)b * H3 + h;
    const float* Xb = X + (size_t)b * H_ + h;
    float*       Ob = Xout + (size_t)b * H_ + h;

    const uint32_t sbase =
        (uint32_t)__cvta_generic_to_shared(&ring[0][tid][0]);
    const uint32_t SLOT = 64 * 4 * 4;     // bytes per ring slot

    // prologue: stage t = 0..D_-1, one commit-group per timestep
    #pragma unroll
    for (int i = 0; i < D_; ++i) {
        const float* u = Ub + (size_t)i * B_ * H3;
        const uint32_t d = sbase + (uint32_t)i * SLOT;
        cp4(d,      u);
        cp4(d + 4,  u + H_);
        cp4(d + 8,  u + 2 * H_);
        cp4(d + 12, Xb + (size_t)i * B_ * H_);
        cp_commit();
    }

    float c = 0.f;
    int rs = 0, ws = 0;                   // read/write ring slots
    for (int t = 0; t < T_; ++t) {
        cp_wait<D_ - 1>();                // group for t complete
        float xt  = ring[rs][tid][0];
        float fp  = ring[rs][tid][1];
        float rp  = ring[rs][tid][2];
        float xin = ring[rs][tid][3];

        // refill slot for t + D_
        const int tp = t + D_;
        if (tp < T_) {
            const float* u = Ub + (size_t)tp * B_ * H3;
            const uint32_t d = sbase + (uint32_t)ws * SLOT;
            cp4(d,      u);
            cp4(d + 4,  u + H_);
            cp4(d + 8,  u + 2 * H_);
            cp4(d + 12, Xb + (size_t)tp * B_ * H_);
        }
        cp_commit();                      // always: keeps group count aligned

        float f  = sigf(fp + vf * c + bf);
        float rr = sigf(rp + vr * c + br);
        float cn = f * c + (1.f - f) * xt;
        Ob[(size_t)t * B_ * H_] = rr * cn + (1.f - rr) * xin;
        c = cn;

        if (++rs == D_) rs = 0;
        if (++ws == D_) ws = 0;
    }
}

// -------- fused conv 6x6 (9ch, pad 3/2) + bias + tanh + h-pool, TT t/block ---
__global__ __launch_bounds__(512) void conv_pool_h(
    const float* __restrict__ X, const float* __restrict__ Wk,
    const float* __restrict__ cb, float* __restrict__ out)
{
    __shared__ float sw[KN * KS * KS];
    __shared__ float xs[KS + TT - 1][H_ + 6];
    __shared__ float buf[KN][H_ + 2];

    const int h  = threadIdx.x;
    const int t0 = blockIdx.x * TT;
    const int b  = blockIdx.y;

    for (int i = h; i < KN * KS * KS; i += 512) sw[i] = Wk[i];

    #pragma unroll
    for (int p = 0; p < KS + TT - 1; ++p) {
        int tt = t0 - 3 + p;
        const float* rowp = X + (size_t)(tt * B_ + b) * H_;
        bool tok = (tt >= 0 && tt < T_);
        for (int idx = h; idx < H_ + 6; idx += 512) {
            int hh = idx - 3;
            xs[p][idx] = (tok && hh >= 0 && hh < H_) ? rowp[hh] : 0.f;
        }
    }
    if (h < KN) { buf[h][0] = -INFINITY; buf[h][H_ + 1] = -INFINITY; }
    __syncthreads();

    #pragma unroll
    for (int dt = 0; dt < TT; ++dt) {
        float acc[KN];
        #pragma unroll
        for (int o = 0; o < KN; ++o) acc[o] = 0.f;
        #pragma unroll
        for (int p = 0; p < KS; ++p) {
            float xv[KS];
            #pragma unroll
            for (int q = 0; q < KS; ++q) xv[q] = xs[dt + p][h + q];
            #pragma unroll
            for (int q = 0; q < KS; ++q) {
                float x = xv[q];
                #pragma unroll
                for (int o = 0; o < KN; ++o)
                    acc[o] = fmaf(x, sw[o * 36 + p * 6 + q], acc[o]);
            }
        }
        #pragma unroll
        for (int o = 0; o < KN; ++o) buf[o][h + 1] = tanhf(acc[o] + cb[o]);
        __syncthreads();
        const int t = t0 + dt;
        #pragma unroll
        for (int o = 0; o < KN; ++o) {
            float m = fmaxf(fmaxf(buf[o][h], buf[o][h + 1]), buf[o][h + 2]);
            out[((size_t)(b * KN + o) * T_ + t) * H_ + h] = m;
        }
        __syncthreads();
    }
}

// t-direction max + transpose into (B*T, H*KN), feature = o*H + h (coalesced)
__global__ void pool_t(const float* __restrict__ in, float* __restrict__ Y)
{
    int h  = blockIdx.x * blockDim.x + threadIdx.x;
    int t  = blockIdx.y;
    int bk = blockIdx.z;
    int b  = bk / KN, o = bk % KN;
    size_t base = ((size_t)bk * T_ + t) * H_ + h;
    float m = in[base];
    if (t > 0)      m = fmaxf(m, in[base - H_]);
    if (t < T_ - 1) m = fmaxf(m, in[base + H_]);
    Y[((size_t)(b * T_ + t)) * FOUT + o * H_ + h] = m;
}

// ---------------- launch ------------------------------------------------------
extern "C" void kernel_launch(void* const* d_in, const int* in_sizes, int n_in,
                              void* d_out, int out_size)
{
    const float* inputs = (const float*)d_in[0];
    const float* W_in   = (const float*)d_in[1];
    const float* b_in   = (const float*)d_in[2];
    const float* W_rnn  = (const float*)d_in[3];
    const float* v_rnn  = (const float*)d_in[4];
    const float* b_rnn  = (const float*)d_in[5];
    const float* conv_k = (const float*)d_in[6];
    const float* conv_b = (const float*)d_in[7];
    const float* W_out  = (const float*)d_in[8];
    const float* b_out  = (const float*)d_in[9];
    float* out = (float*)d_out;

    float *X0, *U, *X1, *X2, *HM, *Y;
    __nv_bfloat16 *BinH, *BinL, *BrnnH, *BrnnL, *BoutH, *BoutL;
    cudaGetSymbolAddress((void**)&X0,   g_X0);
    cudaGetSymbolAddress((void**)&U,    g_U);
    cudaGetSymbolAddress((void**)&X1,   g_X1);
    cudaGetSymbolAddress((void**)&X2,   g_X2);
    cudaGetSymbolAddress((void**)&HM,   g_hmax);
    cudaGetSymbolAddress((void**)&Y,    g_Y);
    cudaGetSymbolAddress((void**)&BinH, g_BinH);
    cudaGetSymbolAddress((void**)&BinL, g_BinL);
    cudaGetSymbolAddress((void**)&BrnnH,g_BrnnH);
    cudaGetSymbolAddress((void**)&BrnnL,g_BrnnL);
    cudaGetSymbolAddress((void**)&BoutH,g_BoutH);
    cudaGetSymbolAddress((void**)&BoutL,g_BoutL);

    // weight prep (K-major bf16 hi/lo)
    prep_w<<<(512*800 + 255)/256, 256>>>(W_in, BinH, BinL, FEAT, H_, 800);
    prep_w<<<(1536*512 + 255)/256, 256>>>(W_rnn, BrnnH, BrnnL, H_, H3, 512);
    prep_w<<<(1536*512 + 255)/256, 256>>>(W_rnn + H_*H3, BrnnH + 1536*512,
                                          BrnnL + 1536*512, H_, H3, 512);
    prep_wout<<<(384*4608 + 255)/256, 256>>>(W_out, BoutH, BoutL);

    // input layer: tanh(inputs @ W_in + b_in) -> X0 (T,B,H)
    hgemm<1><<<dim3(4, 125), 256>>>(
        inputs, BinH, BinL, X0, FEAT, 800, FEAT, H_, H_, b_in, nullptr);

    // SRU layer 0
    hgemm<0><<<dim3(12, 125), 256>>>(
        X0, BrnnH, BrnnL, U, H_, 512, H_, H3, H3, nullptr, nullptr);
    sru_scan_ca<<<(B_*H_)/64, 64>>>(U, X0, X1, v_rnn, b_rnn);

    // SRU layer 1
    hgemm<0><<<dim3(12, 125), 256>>>(
        X1, BrnnH + 1536*512, BrnnL + 1536*512, U, H_, 512, H_, H3, H3,
        nullptr, nullptr);
    sru_scan_ca<<<(B_*H_)/64, 64>>>(U, X1, X2, v_rnn + 2*H_, b_rnn + 2*H_);

    // fused conv + bias + tanh + h-pool (TT timesteps per block)
    conv_pool_h<<<dim3(T_/TT, B_), 512>>>(X2, conv_k, conv_b, HM);

    // t-pool + transpose to (B*T, o*H + h) — fully coalesced
    pool_t<<<dim3(H_/256, T_, B_*KN), 256>>>(HM, Y);

    // output GEMM (257 live cols, padded to 384) + sigmoid gate * inputs
    hgemm<2><<<dim3(3, 125), 256>>>(
        Y, BoutH, BoutL, out, FOUT, FOUT, FOUT, INDIM, INDIM,
        b_out + INDIM, inputs);
}

// round 9
// speedup vs baseline: 1.3092x; 1.0267x over previous
#include <cuda_runtime.h>
#include <cuda_bf16.h>
#include <math.h>
#include <stdint.h>

// Problem constants
#define B_    16
#define T_    1000
#define INDIM 257
#define FEAT  771
#define H_    512
#define H3    1536
#define KN    9
#define KS    6
#define M_    (B_*T_)        // 16000
#define FOUT  (H_*KN)        // 4608
#define TT    8              // fused conv/pool output timesteps per block
#define D_    24             // scan cp.async ring depth

// ---------------- scratch (device globals; no runtime allocation) ------------
__device__ float g_X0[T_*B_*H_];
__device__ float g_U [T_*B_*H3];
__device__ float g_X1[T_*B_*H_];
__device__ float g_X2[T_*B_*H_];
__device__ float g_Y [M_*FOUT];
// bf16 hi/lo weight copies, K-major (N rows x Kp cols), zero-padded
__device__ __nv_bfloat16 g_BinH [512*800],     g_BinL [512*800];
__device__ __nv_bfloat16 g_BrnnH[2*1536*512],  g_BrnnL[2*1536*512];
__device__ __nv_bfloat16 g_BoutH[384*4608],    g_BoutL[384*4608];

__device__ __forceinline__ float sigf(float x) { return 1.f / (1.f + __expf(-x)); }

__device__ __forceinline__ uint32_t pk(__nv_bfloat16 a, __nv_bfloat16 b) {
    return (uint32_t)__bfloat16_as_ushort(b) << 16 | __bfloat16_as_ushort(a);
}
__device__ __forceinline__ void mma16816(float* d, const uint32_t* a,
                                         const uint32_t* b) {
    asm volatile(
        "mma.sync.aligned.m16n8k16.row.col.f32.bf16.bf16.f32 "
        "{%0,%1,%2,%3}, {%4,%5,%6,%7}, {%8,%9}, {%0,%1,%2,%3};"
        : "+f"(d[0]), "+f"(d[1]), "+f"(d[2]), "+f"(d[3])
        : "r"(a[0]), "r"(a[1]), "r"(a[2]), "r"(a[3]), "r"(b[0]), "r"(b[1]));
}

// cp.async helpers
__device__ __forceinline__ void cp4(uint32_t dst, const float* src) {
    asm volatile("cp.async.ca.shared.global [%0], [%1], 4;"
                 :: "r"(dst), "l"(src) : "memory");
}
__device__ __forceinline__ void cp_commit() {
    asm volatile("cp.async.commit_group;" ::: "memory");
}
template <int N>
__device__ __forceinline__ void cp_wait() {
    asm volatile("cp.async.wait_group %0;" :: "n"(N) : "memory");
}

// ---------------- tensor-core GEMM (mma.sync bf16, 2-term fp32 split) --------
template <int MODE>
__global__ __launch_bounds__(256) void hgemm(
    const float* __restrict__ A,
    const __nv_bfloat16* __restrict__ Bh, const __nv_bfloat16* __restrict__ Bl,
    float* __restrict__ C, int Kreal, int Kp, int lda, int ldc, int Ncols,
    const float* __restrict__ bias, const float* __restrict__ gate)
{
    __shared__ uint32_t Ah_s[128*16], Al_s[128*16];
    __shared__ uint32_t Bh_s[128*16], Bl_s[128*16];

    const int tid  = threadIdx.x;
    const int m0   = blockIdx.y * 128;
    const int n0   = blockIdx.x * 128;
    const int wid  = tid >> 5, lane = tid & 31;
    const int wm   = wid >> 2, wn = wid & 3;
    const int quad = lane >> 2, qc = lane & 3;
    const int swq  = quad << 1;

    const int row = tid >> 1, hf = tid & 1;
    const float* Arow = A + (size_t)(m0 + row) * lda + hf * 16;
    const __nv_bfloat16* BhR = Bh + (size_t)(n0 + row) * Kp + hf * 16;
    const __nv_bfloat16* BlR = Bl + (size_t)(n0 + row) * Kp + hf * 16;
    const bool vec = ((lda & 3) == 0) && (Kreal == Kp);

    float acc[4][4][4];
    #pragma unroll
    for (int i = 0; i < 4; ++i)
        #pragma unroll
        for (int j = 0; j < 4; ++j)
            #pragma unroll
            for (int q = 0; q < 4; ++q) acc[i][j][q] = 0.f;

    float ar[16];
    uint4 bhv[2], blv[2];

    {
        if (vec) {
            const float4* p = (const float4*)Arow;
            float4 v0 = p[0], v1 = p[1], v2 = p[2], v3 = p[3];
            ar[0]=v0.x; ar[1]=v0.y; ar[2]=v0.z; ar[3]=v0.w;
            ar[4]=v1.x; ar[5]=v1.y; ar[6]=v1.z; ar[7]=v1.w;
            ar[8]=v2.x; ar[9]=v2.y; ar[10]=v2.z; ar[11]=v2.w;
            ar[12]=v3.x; ar[13]=v3.y; ar[14]=v3.z; ar[15]=v3.w;
        } else {
            #pragma unroll
            for (int t = 0; t < 16; ++t)
                ar[t] = (hf * 16 + t < Kreal) ? Arow[t] : 0.f;
        }
        bhv[0] = ((const uint4*)BhR)[0]; bhv[1] = ((const uint4*)BhR)[1];
        blv[0] = ((const uint4*)BlR)[0]; blv[1] = ((const uint4*)BlR)[1];
    }

    const int nchunks = Kp / 32;
    const int sw_r = (row & 7) << 1;

    for (int ic = 0; ic < nchunks; ++ic) {
        __syncthreads();
        #pragma unroll
        for (int j = 0; j < 8; ++j) {
            float a0 = ar[2*j], a1 = ar[2*j+1];
            __nv_bfloat16 h0 = __float2bfloat16(a0);
            __nv_bfloat16 h1 = __float2bfloat16(a1);
            __nv_bfloat16 l0 = __float2bfloat16(a0 - __bfloat162float(h0));
            __nv_bfloat16 l1 = __float2bfloat16(a1 - __bfloat162float(h1));
            const int idx = row * 16 + ((hf * 8 + j) ^ sw_r);
            Ah_s[idx] = pk(h0, h1);
            Al_s[idx] = pk(l0, l1);
        }
        {
            const uint32_t* bw = (const uint32_t*)bhv;
            const uint32_t* cw = (const uint32_t*)blv;
            #pragma unroll
            for (int j = 0; j < 8; ++j) {
                const int idx = row * 16 + ((hf * 8 + j) ^ sw_r);
                Bh_s[idx] = bw[j];
                Bl_s[idx] = cw[j];
            }
        }
        __syncthreads();

        if (ic + 1 < nchunks) {
            const int k0 = (ic + 1) * 32;
            if (vec) {
                const float4* p = (const float4*)(Arow + k0);
                float4 v0 = p[0], v1 = p[1], v2 = p[2], v3 = p[3];
                ar[0]=v0.x; ar[1]=v0.y; ar[2]=v0.z; ar[3]=v0.w;
                ar[4]=v1.x; ar[5]=v1.y; ar[6]=v1.z; ar[7]=v1.w;
                ar[8]=v2.x; ar[9]=v2.y; ar[10]=v2.z; ar[11]=v2.w;
                ar[12]=v3.x; ar[13]=v3.y; ar[14]=v3.z; ar[15]=v3.w;
            } else {
                #pragma unroll
                for (int t = 0; t < 16; ++t)
                    ar[t] = (k0 + hf * 16 + t < Kreal) ? Arow[k0 + t] : 0.f;
            }
            bhv[0] = ((const uint4*)(BhR + k0))[0];
            bhv[1] = ((const uint4*)(BhR + k0))[1];
            blv[0] = ((const uint4*)(BlR + k0))[0];
            blv[1] = ((const uint4*)(BlR + k0))[1];
        }

        #pragma unroll
        for (int kt = 0; kt < 2; ++kt) {
            const int w0 = kt * 8 + qc, w1 = kt * 8 + 4 + qc;
            uint32_t af[4][4], alf[4][4];
            #pragma unroll
            for (int i = 0; i < 4; ++i) {
                const int r0 = wm * 64 + i * 16 + quad, r1 = r0 + 8;
                const int i00 = r0*16 + (w0^swq), i10 = r1*16 + (w0^swq);
                const int i01 = r0*16 + (w1^swq), i11 = r1*16 + (w1^swq);
                af[i][0]=Ah_s[i00]; af[i][1]=Ah_s[i10];
                af[i][2]=Ah_s[i01]; af[i][3]=Ah_s[i11];
                alf[i][0]=Al_s[i00]; alf[i][1]=Al_s[i10];
                alf[i][2]=Al_s[i01]; alf[i][3]=Al_s[i11];
            }
            uint32_t bfh[4][2], bfl[4][2];
            #pragma unroll
            for (int j = 0; j < 4; ++j) {
                const int rn = wn * 32 + j * 8 + quad;
                const int i0 = rn*16 + (w0^swq), i1 = rn*16 + (w1^swq);
                bfh[j][0]=Bh_s[i0]; bfh[j][1]=Bh_s[i1];
                bfl[j][0]=Bl_s[i0]; bfl[j][1]=Bl_s[i1];
            }
            #pragma unroll
            for (int i = 0; i < 4; ++i)
                #pragma unroll
                for (int j = 0; j < 4; ++j) {
                    mma16816(acc[i][j], af[i],  bfh[j]);
                    mma16816(acc[i][j], af[i],  bfl[j]);
                    mma16816(acc[i][j], alf[i], bfh[j]);
                }
        }
    }

    #pragma unroll
    for (int i = 0; i < 4; ++i) {
        #pragma unroll
        for (int j = 0; j < 4; ++j) {
            const int r0 = m0 + wm * 64 + i * 16 + quad, r1 = r0 + 8;
            const int cc = n0 + wn * 32 + j * 8 + 2 * qc;
            const float* d = acc[i][j];
            if (MODE == 0) {
                *(float2*)(C + (size_t)r0 * ldc + cc) = make_float2(d[0], d[1]);
                *(float2*)(C + (size_t)r1 * ldc + cc) = make_float2(d[2], d[3]);
            } else if (MODE == 1) {
                const int o0 = (r0 % T_) * B_ + (r0 / T_);
                const int o1 = (r1 % T_) * B_ + (r1 / T_);
                const float b0 = bias[cc], b1 = bias[cc + 1];
                *(float2*)(C + (size_t)o0 * H_ + cc) =
                    make_float2(tanhf(d[0] + b0), tanhf(d[1] + b1));
                *(float2*)(C + (size_t)o1 * H_ + cc) =
                    make_float2(tanhf(d[2] + b0), tanhf(d[3] + b1));
            } else {
                #pragma unroll
                for (int q = 0; q < 2; ++q) {
                    const int c = cc + q;
                    if (c < Ncols) {
                        float s0 = sigf(d[q] + bias[c]);
                        float s1 = sigf(d[2 + q] + bias[c]);
                        C[(size_t)r0 * INDIM + c] =
                            s0 * gate[(size_t)r0 * FEAT + INDIM + c];
                        C[(size_t)r1 * INDIM + c] =
                            s1 * gate[(size_t)r1 * FEAT + INDIM + c];
                    }
                }
            }
        }
    }
}

// ---------------- weight prep -------------------------------------------------
__global__ void prep_w(const float* __restrict__ W, __nv_bfloat16* __restrict__ Bh,
                       __nv_bfloat16* __restrict__ Bl, int K, int N, int Kp)
{
    int i = blockIdx.x * blockDim.x + threadIdx.x;
    if (i >= N * Kp) return;
    int n = i / Kp, k = i % Kp;
    float v = (k < K) ? W[(size_t)k * N + n] : 0.f;
    __nv_bfloat16 h = __float2bfloat16(v);
    Bh[i] = h;
    Bl[i] = __float2bfloat16(v - __bfloat162float(h));
}
// Feature axis permuted: k' = o*H + h corresponds to original k = h*KN + o.
__global__ void prep_wout(const float* __restrict__ Wout,
                          __nv_bfloat16* __restrict__ Bh,
                          __nv_bfloat16* __restrict__ Bl)
{
    int i = blockIdx.x * blockDim.x + threadIdx.x;
    if (i >= 384 * 4608) return;
    int n = i / 4608, kp = i % 4608;
    int o = kp / H_, h = kp % H_;
    int k = h * KN + o;
    float v = (n < INDIM) ? Wout[(size_t)k * FEAT + INDIM + n] : 0.f;
    __nv_bfloat16 hh = __float2bfloat16(v);
    Bh[i] = hh;
    Bl[i] = __float2bfloat16(v - __bfloat162float(hh));
}

// ------- SRU recurrence: 1 thread/chain, cp.async ring (depth D_) ------------
__global__ __launch_bounds__(64) void sru_scan_ca(
    const float* __restrict__ U, const float* __restrict__ X,
    float* __restrict__ Xout,
    const float* __restrict__ v, const float* __restrict__ bb)
{
    __shared__ float ring[D_][64][4];

    const int tid = threadIdx.x;
    const int g = blockIdx.x * 64 + tid;
    const int b = g / H_, h = g % H_;
    const float vf = v[h],  vr = v[H_ + h];
    const float bf = bb[h], br = bb[H_ + h];
    const float* Ub = U + (size_t)b * H3 + h;
    const float* Xb = X + (size_t)b * H_ + h;
    float*       Ob = Xout + (size_t)b * H_ + h;

    const uint32_t sbase =
        (uint32_t)__cvta_generic_to_shared(&ring[0][tid][0]);
    const uint32_t SLOT = 64 * 4 * 4;

    #pragma unroll
    for (int i = 0; i < D_; ++i) {
        const float* u = Ub + (size_t)i * B_ * H3;
        const uint32_t d = sbase + (uint32_t)i * SLOT;
        cp4(d,      u);
        cp4(d + 4,  u + H_);
        cp4(d + 8,  u + 2 * H_);
        cp4(d + 12, Xb + (size_t)i * B_ * H_);
        cp_commit();
    }

    float c = 0.f;
    int rs = 0, ws = 0;
    for (int t = 0; t < T_; ++t) {
        cp_wait<D_ - 1>();
        float xt  = ring[rs][tid][0];
        float fp  = ring[rs][tid][1];
        float rp  = ring[rs][tid][2];
        float xin = ring[rs][tid][3];

        const int tp = t + D_;
        if (tp < T_) {
            const float* u = Ub + (size_t)tp * B_ * H3;
            const uint32_t d = sbase + (uint32_t)ws * SLOT;
            cp4(d,      u);
            cp4(d + 4,  u + H_);
            cp4(d + 8,  u + 2 * H_);
            cp4(d + 12, Xb + (size_t)tp * B_ * H_);
        }
        cp_commit();

        float f  = sigf(fp + vf * c + bf);
        float rr = sigf(rp + vr * c + br);
        float cn = f * c + (1.f - f) * xt;
        Ob[(size_t)t * B_ * H_] = rr * cn + (1.f - rr) * xin;
        c = cn;

        if (++rs == D_) rs = 0;
        if (++ws == D_) ws = 0;
    }
}

// ---- fused conv 6x6 (9ch, pad 3/2) + bias + tanh + h-pool + t-pool ----------
// One block: TT output timesteps for one b. Computes TT+2 conv rows; each
// thread keeps a 3-deep register ring of its h-pooled values (t-max is
// elementwise in h). Writes Y directly, coalesced (feature = o*H + h).
// Dynamic smem: sw[324] | xs[(TT+7)][H_+6] | buf[KN][H_+2]
#define XS_W   (H_ + 6)
#define NXROWS (TT + 7)
#define CP_SMEM ((324 + NXROWS * XS_W + KN * (H_ + 2)) * 4)
__global__ __launch_bounds__(512) void conv_pool(
    const float* __restrict__ X, const float* __restrict__ Wk,
    const float* __restrict__ cb, float* __restrict__ Y)
{
    extern __shared__ float dsm[];
    float* sw  = dsm;                        // 324
    float* xs  = sw + 324;                   // NXROWS * XS_W
    float* buf = xs + NXROWS * XS_W;         // KN * (H_+2)

    const int h  = threadIdx.x;
    const int t0 = blockIdx.x * TT;
    const int b  = blockIdx.y;

    for (int i = h; i < KN * KS * KS; i += 512) sw[i] = Wk[i];

    // stage input rows t0-4 .. t0+TT+2
    #pragma unroll
    for (int p = 0; p < NXROWS; ++p) {
        int tt = t0 - 4 + p;
        const float* rowp = X + (size_t)(tt * B_ + b) * H_;
        bool tok = (tt >= 0 && tt < T_);
        for (int idx = h; idx < XS_W; idx += 512) {
            int hh = idx - 3;
            xs[p * XS_W + idx] = (tok && hh >= 0 && hh < H_) ? rowp[hh] : 0.f;
        }
    }
    if (h < KN) {
        buf[h * (H_ + 2)]          = -INFINITY;
        buf[h * (H_ + 2) + H_ + 1] = -INFINITY;
    }
    __syncthreads();

    float ring[3][KN];   // per-thread h-pooled conv rows (register ring)

    #pragma unroll
    for (int dt = 0; dt < TT + 2; ++dt) {
        const int r = t0 - 1 + dt;          // conv row index
        const int slot = dt % 3;
        if (r >= 0 && r < T_) {
            float acc[KN];
            #pragma unroll
            for (int o = 0; o < KN; ++o) acc[o] = 0.f;
            #pragma unroll
            for (int p = 0; p < KS; ++p) {
                const float* xr = xs + (dt + p) * XS_W + h;
                float xv[KS];
                #pragma unroll
                for (int q = 0; q < KS; ++q) xv[q] = xr[q];
                #pragma unroll
                for (int q = 0; q < KS; ++q) {
                    float x = xv[q];
                    #pragma unroll
                    for (int o = 0; o < KN; ++o)
                        acc[o] = fmaf(x, sw[o * 36 + p * 6 + q], acc[o]);
                }
            }
            #pragma unroll
            for (int o = 0; o < KN; ++o)
                buf[o * (H_ + 2) + h + 1] = tanhf(acc[o] + cb[o]);
            __syncthreads();
            #pragma unroll
            for (int o = 0; o < KN; ++o) {
                const float* bp = buf + o * (H_ + 2) + h;
                ring[slot][o] = fmaxf(fmaxf(bp[0], bp[1]), bp[2]);
            }
            __syncthreads();
        } else {
            #pragma unroll
            for (int o = 0; o < KN; ++o) ring[slot][o] = -INFINITY;
        }
        if (dt >= 2) {
            const int t = r - 1;            // output timestep (t0 .. t0+TT-1)
            float* yp = Y + ((size_t)(b * T_ + t)) * FOUT + h;
            #pragma unroll
            for (int o = 0; o < KN; ++o) {
                float m = fmaxf(fmaxf(ring[0][o], ring[1][o]), ring[2][o]);
                yp[o * H_] = m;
            }
        }
    }
}

// ---------------- launch ------------------------------------------------------
extern "C" void kernel_launch(void* const* d_in, const int* in_sizes, int n_in,
                              void* d_out, int out_size)
{
    const float* inputs = (const float*)d_in[0];
    const float* W_in   = (const float*)d_in[1];
    const float* b_in   = (const float*)d_in[2];
    const float* W_rnn  = (const float*)d_in[3];
    const float* v_rnn  = (const float*)d_in[4];
    const float* b_rnn  = (const float*)d_in[5];
    const float* conv_k = (const float*)d_in[6];
    const float* conv_b = (const float*)d_in[7];
    const float* W_out  = (const float*)d_in[8];
    const float* b_out  = (const float*)d_in[9];
    float* out = (float*)d_out;

    float *X0, *U, *X1, *X2, *Y;
    __nv_bfloat16 *BinH, *BinL, *BrnnH, *BrnnL, *BoutH, *BoutL;
    cudaGetSymbolAddress((void**)&X0,   g_X0);
    cudaGetSymbolAddress((void**)&U,    g_U);
    cudaGetSymbolAddress((void**)&X1,   g_X1);
    cudaGetSymbolAddress((void**)&X2,   g_X2);
    cudaGetSymbolAddress((void**)&Y,    g_Y);
    cudaGetSymbolAddress((void**)&BinH, g_BinH);
    cudaGetSymbolAddress((void**)&BinL, g_BinL);
    cudaGetSymbolAddress((void**)&BrnnH,g_BrnnH);
    cudaGetSymbolAddress((void**)&BrnnL,g_BrnnL);
    cudaGetSymbolAddress((void**)&BoutH,g_BoutH);
    cudaGetSymbolAddress((void**)&BoutL,g_BoutL);

    cudaFuncSetAttribute(conv_pool,
                         cudaFuncAttributeMaxDynamicSharedMemorySize, CP_SMEM);

    // weight prep (K-major bf16 hi/lo)
    prep_w<<<(512*800 + 255)/256, 256>>>(W_in, BinH, BinL, FEAT, H_, 800);
    prep_w<<<(1536*512 + 255)/256, 256>>>(W_rnn, BrnnH, BrnnL, H_, H3, 512);
    prep_w<<<(1536*512 + 255)/256, 256>>>(W_rnn + H_*H3, BrnnH + 1536*512,
                                          BrnnL + 1536*512, H_, H3, 512);
    prep_wout<<<(384*4608 + 255)/256, 256>>>(W_out, BoutH, BoutL);

    // input layer: tanh(inputs @ W_in + b_in) -> X0 (T,B,H)
    hgemm<1><<<dim3(4, 125), 256>>>(
        inputs, BinH, BinL, X0, FEAT, 800, FEAT, H_, H_, b_in, nullptr);

    // SRU layer 0
    hgemm<0><<<dim3(12, 125), 256>>>(
        X0, BrnnH, BrnnL, U, H_, 512, H_, H3, H3, nullptr, nullptr);
    sru_scan_ca<<<(B_*H_)/64, 64>>>(U, X0, X1, v_rnn, b_rnn);

    // SRU layer 1
    hgemm<0><<<dim3(12, 125), 256>>>(
        X1, BrnnH + 1536*512, BrnnL + 1536*512, U, H_, 512, H_, H3, H3,
        nullptr, nullptr);
    sru_scan_ca<<<(B_*H_)/64, 64>>>(U, X1, X2, v_rnn + 2*H_, b_rnn + 2*H_);

    // fused conv + bias + tanh + h-pool + t-pool -> Y (B*T, o*H + h)
    conv_pool<<<dim3(T_/TT, B_), 512, CP_SMEM>>>(X2, conv_k, conv_b, Y);

    // output GEMM (257 live cols, padded to 384) + sigmoid gate * inputs
    hgemm<2><<<dim3(3, 125), 256>>>(
        Y, BoutH, BoutL, out, FOUT, FOUT, FOUT, INDIM, INDIM,
        b_out + INDIM, inputs);
}